// round 9
// baseline (speedup 1.0000x reference)
#include <cuda_runtime.h>
#include <math.h>

// ---------------------------------------------------------------------------
// Problem constants
// ---------------------------------------------------------------------------
#define BATCH   64
#define TFULL   512
#define THARM   256
#define TSPIKE  256
#define NINP    64
#define NHID    1024
#define DTF     0.042f
#define THRESH  0.008f
#define RESETV  0.001f
#define LEAKC   0.00105f      /* R_MEM * C_MEM * DT */

#define GRID_H  128           /* persistent CTAs, 8 h-cols each            */
#define BLK_H   512           /* 16 warps; warp = 8-k slice per chunk      */
#define NCH     8             /* chunks per step, 128 k each               */
#define CHF     8192          /* floats per chunk (128 k x 64 b) = 32 KB   */

// ---------------------------------------------------------------------------
// Device scratch (static — no cudaMalloc anywhere)
// ---------------------------------------------------------------------------
__device__ float    g_xw[(size_t)THARM * BATCH * NHID]; // x @ x2h  (64 MB)
__device__ float    g_hyBK[2][BATCH * NHID];            // hy state [b][k]
__device__ float    g_hzF[BATCH * NHID];                // final hz [b][h]
__device__ float    g_hyW[BATCH * NHID];                // hy_final @ h2h
__device__ unsigned g_flag[NCH];                        // per-chunk epochs

// ---------------------------------------------------------------------------
// packed f32x2 helpers
// ---------------------------------------------------------------------------
__device__ __forceinline__ void upk2(unsigned long long v, float &lo, float &hi) {
    asm("mov.b64 {%0, %1}, %2;" : "=f"(lo), "=f"(hi) : "l"(v));
}
__device__ __forceinline__ void fma2(unsigned long long &d,
                                     unsigned long long a,
                                     unsigned long long b) {
    asm("fma.rn.f32x2 %0, %1, %2, %0;" : "+l"(d) : "l"(a), "l"(b));
}

// ---------------------------------------------------------------------------
// async-copy / flag primitives
// ---------------------------------------------------------------------------
__device__ __forceinline__ void cp_async16(float* dst, const float* src) {
    unsigned d = (unsigned)__cvta_generic_to_shared(dst);
    asm volatile("cp.async.cg.shared.global [%0], [%1], 16;"
                 :: "r"(d), "l"(src));
}
__device__ __forceinline__ void cp_commit() {
    asm volatile("cp.async.commit_group;");
}
template<int N> __device__ __forceinline__ void cp_wait() {
    asm volatile("cp.async.wait_group %0;" :: "n"(N));
}
__device__ __forceinline__ unsigned ld_acq(const unsigned* p) {
    unsigned v;
    asm volatile("ld.acquire.gpu.global.u32 %0, [%1];" : "=r"(v) : "l"(p));
    return v;
}
__device__ __forceinline__ void red_release(unsigned* p) {
    asm volatile("red.release.gpu.global.add.u32 [%0], 1;" :: "l"(p));
}
__device__ __forceinline__ void poll_flag(int c, unsigned tgt) {
    if (ld_acq(&g_flag[c]) >= tgt) return;
    while (ld_acq(&g_flag[c]) < tgt) __nanosleep(40);
}

// ---------------------------------------------------------------------------
// xw[t][b][h] = x[b,t,:] @ x2h[:,h]  for t < 256.  grid=256, blk=256.
// Block 0 also resets the chunk flags for this launch (graph-replay safe).
// ---------------------------------------------------------------------------
__global__ void __launch_bounds__(256)
xw_kernel(const float* __restrict__ x, const float* __restrict__ x2h) {
    __shared__ float2 x_s[BATCH * NINP];

    const int t   = blockIdx.x;
    const int tid = threadIdx.x;

    if (blockIdx.x == 0 && tid < NCH) g_flag[tid] = 0u;

    for (int i = tid; i < BATCH * NINP; i += 256) {
        int b = i >> 6, ii = i & 63;
        float v = x[((size_t)b * TFULL + t) * NINP + ii];
        x_s[i] = make_float2(v, v);
    }
    __syncthreads();

    const int h0 = tid * 4;

    for (int bg = 0; bg < 8; bg++) {
        unsigned long long acc[8][2];
        #pragma unroll
        for (int bb = 0; bb < 8; bb++) { acc[bb][0] = 0ull; acc[bb][1] = 0ull; }

        #pragma unroll 4
        for (int k = 0; k < NINP; k++) {
            ulonglong2 w = *(const ulonglong2*)&x2h[k * NHID + h0];
            #pragma unroll
            for (int bb = 0; bb < 8; bb++) {
                unsigned long long xv =
                    *(const unsigned long long*)&x_s[(bg * 8 + bb) * NINP + k];
                fma2(acc[bb][0], xv, w.x);
                fma2(acc[bb][1], xv, w.y);
            }
        }
        #pragma unroll
        for (int bb = 0; bb < 8; bb++) {
            int b = bg * 8 + bb;
            float o0, o1, o2, o3;
            upk2(acc[bb][0], o0, o1);
            upk2(acc[bb][1], o2, o3);
            *(float4*)&g_xw[((size_t)t * BATCH + b) * NHID + h0] =
                make_float4(o0, o1, o2, o3);
        }
    }
}

// ---------------------------------------------------------------------------
// stage one 32 KB chunk cc (128 k x 64 b) into a swizzled smem buffer.
// global [b][k]; smem: row b = 128 floats, granule g stored at g XOR (b&31).
// 512 threads -> 4 cp.async16 each.
// ---------------------------------------------------------------------------
__device__ __forceinline__ void fill_chunk(const float* __restrict__ hySrc,
                                           int cc, float* __restrict__ buf,
                                           int tid) {
    #pragma unroll
    for (int i = 0; i < 4; i++) {
        int G = tid + (i << 9);            // 0..2047
        int b = G >> 5, g = G & 31;
        const float* src = hySrc + ((size_t)b << 10) + (cc << 7) + (g << 2);
        float*       dst = buf + (b << 7) + (((g ^ (b & 31)) & 31) << 2);
        cp_async16(dst, src);
    }
}

// ---------------------------------------------------------------------------
// warp-sliced matvec: 16 warps, warp owns an 8-k slice (2 granules) per
// chunk; lane = b (rows b and b+32), all 8 CTA cols. Cross-warp reduction
// via smem (ring slot 0 — last read at c=4, safe). Output: one scalar per
// thread for (b = tid>>3, col = tid&7).
// ---------------------------------------------------------------------------
__device__ __forceinline__ float matvec512(const float* __restrict__ hySrc,
                                           const float* __restrict__ w_s,
                                           float* __restrict__ bufs,
                                           int tid, int lane, int wid, int s,
                                           unsigned tgt) {
    unsigned long long aA[8], aB[8];
    #pragma unroll
    for (int q = 0; q < 8; q++) { aA[q] = 0ull; aB[q] = 0ull; }

    poll_flag(s, tgt);           fill_chunk(hySrc, s,           bufs,       tid); cp_commit();
    poll_flag((s + 1) & 7, tgt); fill_chunk(hySrc, (s + 1) & 7, bufs + CHF, tid); cp_commit();

    for (int c = 0; c < NCH; c++) {
        const int cc = (s + c) & 7;
        if (c < NCH - 2) {
            const int cf = (s + c + 2) & 7;
            poll_flag(cf, tgt);
            fill_chunk(hySrc, cf, bufs + ((c + 2) & 3) * CHF, tid);
            cp_commit();
            cp_wait<2>();
        } else if (c == NCH - 2) {
            cp_wait<1>();
        } else {
            cp_wait<0>();
        }
        __syncthreads();

        const float* buf = bufs + (c & 3) * CHF;
        const float* hb0 = buf + (lane << 7);          // b = lane
        const float* hb1 = buf + ((lane + 32) << 7);   // b = lane+32
        const float* wb  = w_s + (cc << 7) + (wid << 3);

        #pragma unroll
        for (int i = 0; i < 2; i++) {
            const int g  = (wid << 1) + i;             // k-granule in chunk
            const int go = ((g ^ lane) & 31) << 2;
            ulonglong2 h0 = *(const ulonglong2*)(hb0 + go);
            ulonglong2 h1 = *(const ulonglong2*)(hb1 + go);
            #pragma unroll
            for (int q = 0; q < 8; q++) {
                ulonglong2 wv = *(const ulonglong2*)(wb + (q << 10) + (i << 2));
                fma2(aA[q], h0.x, wv.x);
                fma2(aA[q], h0.y, wv.y);
                fma2(aB[q], h1.x, wv.x);
                fma2(aB[q], h1.y, wv.y);
            }
        }
        // slot (c&3) refilled at iter c+2, after the barrier of c+1 -> safe
    }

    // ---- cross-warp reduction (slot 0: last read at c=4, barriers passed) --
    float* red = bufs;    // 16 warps x 512 floats = 32 KB
    float pA[8], pB[8];
    #pragma unroll
    for (int q = 0; q < 8; q++) {
        float lo, hi;
        upk2(aA[q], lo, hi); pA[q] = lo + hi;
        upk2(aB[q], lo, hi); pB[q] = lo + hi;
    }
    float* myr = red + (wid << 9) + (lane << 3);
    *(float4*)(myr)       = make_float4(pA[0], pA[1], pA[2], pA[3]);
    *(float4*)(myr + 4)   = make_float4(pA[4], pA[5], pA[6], pA[7]);
    *(float4*)(myr + 256) = make_float4(pB[0], pB[1], pB[2], pB[3]);
    *(float4*)(myr + 260) = make_float4(pB[4], pB[5], pB[6], pB[7]);
    __syncthreads();

    const int b   = tid >> 3;
    const int q   = tid & 7;
    const int ofs = ((b & 32) ? 256 : 0) + ((b & 31) << 3) + q;
    float ssum = 0.f;
    #pragma unroll
    for (int w = 0; w < 16; w++)
        ssum += red[(w << 9) + ofs];
    __syncthreads();   // red reads done before slot 0 is refilled next step
    return ssum;
}

// ---------------------------------------------------------------------------
// persistent harmonic kernel. grid=128, blk=512, smem=160 KB.
// Thread owns output (b = tid>>3, j = J0 + (tid&7)).
// ---------------------------------------------------------------------------
__global__ void __launch_bounds__(BLK_H, 1)
harm_persist(const float* __restrict__ W,
             const float* __restrict__ bias,
             const float* __restrict__ gamma,
             const float* __restrict__ epsv,
             float* __restrict__ hys,
             float* __restrict__ hzs) {
    extern __shared__ float sm[];
    float* w_s  = sm;              // [8 cols][1024 k]  32 KB
    float* bufs = sm + NHID * 8;   // 4 x 32 KB ring

    const int tid  = threadIdx.x;
    const int lane = tid & 31;
    const int wid  = tid >> 5;
    const int J0   = blockIdx.x * 8;
    const int s    = blockIdx.x & 7;       // staggered chunk start

    // one-time: W columns into smem, layout [local col][k]
    for (int i = tid; i < NHID * 8; i += BLK_H) {
        int cc = i & 7, k = i >> 3;
        w_s[cc * NHID + k] = W[(size_t)k * NHID + J0 + cc];
    }

    const int b = tid >> 3;
    const int j = J0 + (tid & 7);

    const float bs = bias[j];
    const float gm = gamma[j];
    const float ep = epsv[j];

    float hy = 0.f, hz = 0.f;

    __syncthreads();

    for (int t = 0; t < THARM; t++) {
        float acc = 0.f;
        if (t > 0)
            acc = matvec512(g_hyBK[(t - 1) & 1], w_s, bufs, tid, lane, wid, s,
                            16u * (unsigned)t);

        const float xw = g_xw[((size_t)t * BATCH + b) * NHID + j];

        float val = tanhf(acc + xw + bs);
        hz = hz + DTF * ((val - gm * hy) - ep * hz);
        hy = hy + DTF * hz;

        // publish hy [b][k] for next step — only consumer-visible store
        g_hyBK[t & 1][((size_t)b << 10) + j] = hy;

        __syncthreads();                    // CTA's hy stores all issued
        if (tid == 0) red_release(&g_flag[blockIdx.x >> 4]);

        // trajectory outputs (off the inter-CTA critical path)
        hys[((size_t)b * TFULL + t) * NHID + j] = hy;
        hzs[((size_t)b * TFULL + t) * NHID + j] = hz;
    }

    // final: hyW = hy(255) @ W  (buffer 1, epoch 256)
    {
        float acc = matvec512(g_hyBK[1], w_s, bufs, tid, lane, wid, s,
                              16u * 256u);
        g_hyW[((size_t)b << 10) + j] = acc;
        g_hzF[((size_t)b << 10) + j] = hz;
    }
}

// ---------------------------------------------------------------------------
// spiking LIF phase + constant hy/hz tails. 2 h per thread, float2 I/O.
// grid = 128, block = 256  -> 32768 threads.
// ---------------------------------------------------------------------------
__global__ void __launch_bounds__(256)
spike_kernel(float* __restrict__ us,
             float* __restrict__ spk,
             float* __restrict__ hys,
             float* __restrict__ hzs) {
    const int gid = blockIdx.x * 256 + threadIdx.x;  // 0..32767
    const int b   = gid >> 9;
    const int h0  = (gid & 511) << 1;
    const size_t base = (size_t)b * NHID + h0;

    const float2 hyw = *(const float2*)&g_hyW[base];
    const float2 hyf = *(const float2*)&g_hyBK[1][base];
    const float2 hzf = *(const float2*)&g_hzF[base];

    const float* xp  = g_xw + base;
    float* up  = us  + (size_t)b * TSPIKE * NHID + h0;
    float* sp  = spk + (size_t)b * TSPIKE * NHID + h0;
    float* hyp = hys + ((size_t)b * TFULL + THARM) * NHID + h0;
    float* hzp = hzs + ((size_t)b * TFULL + THARM) * NHID + h0;

    float u0 = 0.f, u1 = 0.f;

    #pragma unroll 4
    for (int t = 0; t < TSPIKE; t++) {
        float2 xin = *(const float2*)(xp + (size_t)t * BATCH * NHID);
        float s0 = (u0 > THRESH) ? 1.0f : 0.0f;
        float s1 = (u1 > THRESH) ? 1.0f : 0.0f;
        if (u0 > THRESH) u0 = RESETV;
        if (u1 > THRESH) u1 = RESETV;
        u0 = u0 + ((hyw.x + xin.x) - u0) * LEAKC;
        u1 = u1 + ((hyw.y + xin.y) - u1) * LEAKC;
        size_t to = (size_t)t * NHID;
        *(float2*)(up + to)  = make_float2(u0, u1);
        *(float2*)(sp + to)  = make_float2(s0, s1);
        *(float2*)(hyp + to) = hyf;
        *(float2*)(hzp + to) = hzf;
    }
}

// ---------------------------------------------------------------------------
// launcher: xw(+flag reset) -> persistent harmonic -> spike
// ---------------------------------------------------------------------------
extern "C" void kernel_launch(void* const* d_in, const int* in_sizes, int n_in,
                              void* d_out, int out_size) {
    const float* x    = (const float*)d_in[0];
    const float* x2h  = (const float*)d_in[1];
    const float* h2h  = (const float*)d_in[2];
    const float* bias = (const float*)d_in[3];
    const float* gam  = (const float*)d_in[4];
    const float* eps  = (const float*)d_in[5];

    float* out = (float*)d_out;
    float* hys = out;                                     // B*T*H
    float* hzs = hys + (size_t)BATCH * TFULL * NHID;      // B*T*H
    float* us  = hzs + (size_t)BATCH * TFULL * NHID;      // B*Ts*H
    float* spk = us  + (size_t)BATCH * TSPIKE * NHID;     // B*Ts*H

    static int smem_set = 0;
    const int smem_bytes = (NHID * 8 + 4 * CHF) * sizeof(float);  // 160 KB
    if (!smem_set) {
        cudaFuncSetAttribute(harm_persist,
                             cudaFuncAttributeMaxDynamicSharedMemorySize,
                             smem_bytes);
        smem_set = 1;
    }

    xw_kernel<<<THARM, 256>>>(x, x2h);
    harm_persist<<<GRID_H, BLK_H, smem_bytes>>>(h2h, bias, gam, eps, hys, hzs);
    spike_kernel<<<128, 256>>>(us, spk, hys, hzs);
}

// round 10
// speedup vs baseline: 1.2849x; 1.2849x over previous
#include <cuda_runtime.h>
#include <math.h>

// ---------------------------------------------------------------------------
// Problem constants
// ---------------------------------------------------------------------------
#define BATCH   64
#define TFULL   512
#define THARM   256
#define TSPIKE  256
#define NINP    64
#define NHID    1024
#define DTF     0.042f
#define THRESH  0.008f
#define RESETV  0.001f
#define LEAKC   0.00105f      /* R_MEM * C_MEM * DT */

#define GRID_H  128           /* persistent CTAs, 8 h-cols each            */
#define BLK_H   256           /* 8 warps; warp owns a 16-k slice per chunk */
#define NCH     8             /* chunks per step, 128 k each               */

// ---------------------------------------------------------------------------
// Device scratch (static — no cudaMalloc anywhere)
// ---------------------------------------------------------------------------
__device__ float    g_xw[(size_t)THARM * BATCH * NHID]; // x @ x2h  (64 MB)
__device__ float    g_hyT[2][NHID * BATCH];             // hy state [k][b] (transposed)
__device__ float    g_hzF[BATCH * NHID];                // final hz [b][h]
__device__ float    g_hyW[BATCH * NHID];                // hy_final @ h2h [b][h]
__device__ unsigned g_flag[NCH];                        // per-chunk epochs

// ---------------------------------------------------------------------------
// packed f32x2 helpers
// ---------------------------------------------------------------------------
__device__ __forceinline__ void upk2(unsigned long long v, float &lo, float &hi) {
    asm("mov.b64 {%0, %1}, %2;" : "=f"(lo), "=f"(hi) : "l"(v));
}
__device__ __forceinline__ unsigned long long pkdup(float v) {
    unsigned long long r;
    asm("mov.b64 %0, {%1, %1};" : "=l"(r) : "f"(v));
    return r;
}
__device__ __forceinline__ void fma2(unsigned long long &d,
                                     unsigned long long a,
                                     unsigned long long b) {
    asm("fma.rn.f32x2 %0, %1, %2, %0;" : "+l"(d) : "l"(a), "l"(b));
}

// ---------------------------------------------------------------------------
// flag primitives (monotonic per-chunk epochs through L2)
// ---------------------------------------------------------------------------
__device__ __forceinline__ unsigned ld_acq(const unsigned* p) {
    unsigned v;
    asm volatile("ld.acquire.gpu.global.u32 %0, [%1];" : "=r"(v) : "l"(p));
    return v;
}
__device__ __forceinline__ void red_release(unsigned* p) {
    asm volatile("red.release.gpu.global.add.u32 [%0], 1;" :: "l"(p));
}
__device__ __forceinline__ void poll_flag(int c, unsigned tgt) {
    if (ld_acq(&g_flag[c]) >= tgt) return;
    while (ld_acq(&g_flag[c]) < tgt) __nanosleep(40);
}

// ---------------------------------------------------------------------------
// xw[t][b][h] = x[b,t,:] @ x2h[:,h]  for t < 256.  grid=256, blk=256.
// Block 0 also resets the chunk flags for this launch (graph-replay safe;
// harm_persist launches after in the same stream).
// ---------------------------------------------------------------------------
__global__ void __launch_bounds__(256)
xw_kernel(const float* __restrict__ x, const float* __restrict__ x2h) {
    __shared__ float2 x_s[BATCH * NINP];

    const int t   = blockIdx.x;
    const int tid = threadIdx.x;

    if (blockIdx.x == 0 && tid < NCH) g_flag[tid] = 0u;

    for (int i = tid; i < BATCH * NINP; i += 256) {
        int b = i >> 6, ii = i & 63;
        float v = x[((size_t)b * TFULL + t) * NINP + ii];
        x_s[i] = make_float2(v, v);
    }
    __syncthreads();

    const int h0 = tid * 4;

    for (int bg = 0; bg < 8; bg++) {
        unsigned long long acc[8][2];
        #pragma unroll
        for (int bb = 0; bb < 8; bb++) { acc[bb][0] = 0ull; acc[bb][1] = 0ull; }

        #pragma unroll 4
        for (int k = 0; k < NINP; k++) {
            ulonglong2 w = *(const ulonglong2*)&x2h[k * NHID + h0];
            #pragma unroll
            for (int bb = 0; bb < 8; bb++) {
                unsigned long long xv =
                    *(const unsigned long long*)&x_s[(bg * 8 + bb) * NINP + k];
                fma2(acc[bb][0], xv, w.x);
                fma2(acc[bb][1], xv, w.y);
            }
        }
        #pragma unroll
        for (int bb = 0; bb < 8; bb++) {
            int b = bg * 8 + bb;
            float o0, o1, o2, o3;
            upk2(acc[bb][0], o0, o1);
            upk2(acc[bb][1], o2, o3);
            *(float4*)&g_xw[((size_t)t * BATCH + b) * NHID + h0] =
                make_float4(o0, o1, o2, o3);
        }
    }
}

// ---------------------------------------------------------------------------
// barrier-free matvec: 8 warps, warp wid owns k-slice [cc*128+wid*16, +16)
// of each chunk cc. hy read DIRECTLY from L2 via coalesced __ldcg (layout
// [k][b]); W broadcast from smem [k][8cols]. acc packed over column pairs.
// Per-warp independent flag polls — no per-chunk CTA barrier.
// Outputs: o0 for (b = tid>>3, col = tid&7), o1 for (b+32, same col).
// One __syncthreads inside (reduction); caller provides the post-read one.
// ---------------------------------------------------------------------------
__device__ __forceinline__ void matvec(const float* __restrict__ hyT,
                                       const float* __restrict__ w_s,
                                       float* __restrict__ red,
                                       int tid, int lane, int wid, int s,
                                       unsigned tgt, float &o0, float &o1) {
    unsigned long long aA[4], aB[4];
    #pragma unroll
    for (int q = 0; q < 4; q++) { aA[q] = 0ull; aB[q] = 0ull; }

    for (int c = 0; c < NCH; c++) {
        const int cc = (s + c) & 7;
        poll_flag(cc, tgt);

        const int kbase = (cc << 7) + (wid << 4);          // global k start
        const float* hp = hyT + ((size_t)kbase << 6) + lane;
        float h0[16], h1[16];
        #pragma unroll
        for (int k = 0; k < 16; k++) {
            h0[k] = __ldcg(hp + (k << 6));
            h1[k] = __ldcg(hp + (k << 6) + 32);
        }
        const float* wp = w_s + (kbase << 3);
        #pragma unroll
        for (int k = 0; k < 16; k++) {
            unsigned long long hv0 = pkdup(h0[k]);
            unsigned long long hv1 = pkdup(h1[k]);
            ulonglong2 wA = *(const ulonglong2*)(wp + (k << 3));
            ulonglong2 wB = *(const ulonglong2*)(wp + (k << 3) + 4);
            fma2(aA[0], hv0, wA.x); fma2(aA[1], hv0, wA.y);
            fma2(aA[2], hv0, wB.x); fma2(aA[3], hv0, wB.y);
            fma2(aB[0], hv1, wA.x); fma2(aB[1], hv1, wA.y);
            fma2(aB[2], hv1, wB.x); fma2(aB[3], hv1, wB.y);
        }
    }

    // ---- cross-warp reduction through smem ----
    float pA[8], pB[8];
    #pragma unroll
    for (int q = 0; q < 4; q++) {
        upk2(aA[q], pA[2 * q], pA[2 * q + 1]);
        upk2(aB[q], pB[2 * q], pB[2 * q + 1]);
    }
    float* myr = red + (wid << 9) + (lane << 3);
    *(float4*)(myr)       = make_float4(pA[0], pA[1], pA[2], pA[3]);
    *(float4*)(myr + 4)   = make_float4(pA[4], pA[5], pA[6], pA[7]);
    *(float4*)(myr + 256) = make_float4(pB[0], pB[1], pB[2], pB[3]);
    *(float4*)(myr + 260) = make_float4(pB[4], pB[5], pB[6], pB[7]);
    __syncthreads();

    float s0 = 0.f, s1 = 0.f;
    #pragma unroll
    for (int w = 0; w < 8; w++) {
        s0 += red[(w << 9) + tid];
        s1 += red[(w << 9) + 256 + tid];
    }
    o0 = s0; o1 = s1;
    // caller's pre-release __syncthreads protects 'red' for the next step
}

// ---------------------------------------------------------------------------
// persistent harmonic kernel. grid=128, blk=256, smem=48 KB.
// Thread owns outputs (bA = tid>>3, j = J0+(tid&7)) and (bB = bA+32, j).
// ---------------------------------------------------------------------------
__global__ void __launch_bounds__(BLK_H, 1)
harm_persist(const float* __restrict__ W,
             const float* __restrict__ bias,
             const float* __restrict__ gamma,
             const float* __restrict__ epsv,
             float* __restrict__ hys,
             float* __restrict__ hzs) {
    extern __shared__ float sm[];
    float* w_s = sm;               // [1024 k][8 cols]  32 KB
    float* red = sm + NHID * 8;    // 8 warps x 512     16 KB

    const int tid  = threadIdx.x;
    const int lane = tid & 31;
    const int wid  = tid >> 5;
    const int J0   = blockIdx.x * 8;
    const int s    = blockIdx.x & 7;       // staggered chunk start

    // one-time: W columns into smem, layout [k][8 local cols]
    for (int i = tid; i < NHID * 8; i += BLK_H) {
        int cc = i & 7, k = i >> 3;
        w_s[(k << 3) + cc] = W[(size_t)k * NHID + J0 + cc];
    }

    const int bA = tid >> 3;       // 0..31
    const int bB = bA + 32;
    const int jl = tid & 7;        // local col
    const int j  = J0 + jl;

    const float bs = bias[j];
    const float gm = gamma[j];
    const float ep = epsv[j];

    float hyA = 0.f, hzA = 0.f, hyB = 0.f, hzB = 0.f;

    __syncthreads();

    for (int t = 0; t < THARM; t++) {
        float o0 = 0.f, o1 = 0.f;
        if (t > 0)
            matvec(g_hyT[(t - 1) & 1], w_s, red, tid, lane, wid, s,
                   16u * (unsigned)t, o0, o1);

        const float xwA = g_xw[((size_t)t * BATCH + bA) * NHID + j];
        const float xwB = g_xw[((size_t)t * BATCH + bB) * NHID + j];

        float vA = tanhf(o0 + xwA + bs);
        float vB = tanhf(o1 + xwB + bs);
        hzA = hzA + DTF * ((vA - gm * hyA) - ep * hzA);
        hyA = hyA + DTF * hzA;
        hzB = hzB + DTF * ((vB - gm * hyB) - ep * hzB);
        hyB = hyB + DTF * hzB;

        // publish hy transposed [k][b] for the next step
        float* hyOut = g_hyT[t & 1];
        hyOut[(j << 6) + bA] = hyA;
        hyOut[(j << 6) + bB] = hyB;

        __syncthreads();                    // red reads + hy stores complete
        if (tid == 0) red_release(&g_flag[blockIdx.x >> 4]);

        // trajectory outputs (off the inter-CTA critical path)
        hys[((size_t)bA * TFULL + t) * NHID + j] = hyA;
        hzs[((size_t)bA * TFULL + t) * NHID + j] = hzA;
        hys[((size_t)bB * TFULL + t) * NHID + j] = hyB;
        hzs[((size_t)bB * TFULL + t) * NHID + j] = hzB;
    }

    // final: hyW = hy(255) @ W  (buffer 1, epoch 16*256)
    {
        float o0, o1;
        matvec(g_hyT[1], w_s, red, tid, lane, wid, s, 16u * 256u, o0, o1);
        g_hyW[((size_t)bA << 10) + j] = o0;
        g_hyW[((size_t)bB << 10) + j] = o1;
        g_hzF[((size_t)bA << 10) + j] = hzA;
        g_hzF[((size_t)bB << 10) + j] = hzB;
    }
}

// ---------------------------------------------------------------------------
// spiking LIF phase + constant hy/hz tails. 2 h per thread, float2 I/O.
// grid = 128, block = 256  -> 32768 threads.
// ---------------------------------------------------------------------------
__global__ void __launch_bounds__(256)
spike_kernel(float* __restrict__ us,
             float* __restrict__ spk,
             float* __restrict__ hys,
             float* __restrict__ hzs) {
    const int gid = blockIdx.x * 256 + threadIdx.x;  // 0..32767
    const int b   = gid >> 9;
    const int h0  = (gid & 511) << 1;
    const size_t base = (size_t)b * NHID + h0;

    const float2 hyw = *(const float2*)&g_hyW[base];
    const float2 hzf = *(const float2*)&g_hzF[base];
    const float2 hyf = make_float2(g_hyT[1][(h0 << 6) + b],
                                   g_hyT[1][((h0 + 1) << 6) + b]);

    const float* xp  = g_xw + base;
    float* up  = us  + (size_t)b * TSPIKE * NHID + h0;
    float* sp  = spk + (size_t)b * TSPIKE * NHID + h0;
    float* hyp = hys + ((size_t)b * TFULL + THARM) * NHID + h0;
    float* hzp = hzs + ((size_t)b * TFULL + THARM) * NHID + h0;

    float u0 = 0.f, u1 = 0.f;

    #pragma unroll 4
    for (int t = 0; t < TSPIKE; t++) {
        float2 xin = *(const float2*)(xp + (size_t)t * BATCH * NHID);
        float s0 = (u0 > THRESH) ? 1.0f : 0.0f;
        float s1 = (u1 > THRESH) ? 1.0f : 0.0f;
        if (u0 > THRESH) u0 = RESETV;
        if (u1 > THRESH) u1 = RESETV;
        u0 = u0 + ((hyw.x + xin.x) - u0) * LEAKC;
        u1 = u1 + ((hyw.y + xin.y) - u1) * LEAKC;
        size_t to = (size_t)t * NHID;
        *(float2*)(up + to)  = make_float2(u0, u1);
        *(float2*)(sp + to)  = make_float2(s0, s1);
        *(float2*)(hyp + to) = hyf;
        *(float2*)(hzp + to) = hzf;
    }
}

// ---------------------------------------------------------------------------
// launcher: xw(+flag reset) -> persistent harmonic -> spike
// ---------------------------------------------------------------------------
extern "C" void kernel_launch(void* const* d_in, const int* in_sizes, int n_in,
                              void* d_out, int out_size) {
    const float* x    = (const float*)d_in[0];
    const float* x2h  = (const float*)d_in[1];
    const float* h2h  = (const float*)d_in[2];
    const float* bias = (const float*)d_in[3];
    const float* gam  = (const float*)d_in[4];
    const float* eps  = (const float*)d_in[5];

    float* out = (float*)d_out;
    float* hys = out;                                     // B*T*H
    float* hzs = hys + (size_t)BATCH * TFULL * NHID;      // B*T*H
    float* us  = hzs + (size_t)BATCH * TFULL * NHID;      // B*Ts*H
    float* spk = us  + (size_t)BATCH * TSPIKE * NHID;     // B*Ts*H

    static int smem_set = 0;
    const int smem_bytes = (NHID * 8 + 8 * 512) * sizeof(float);  // 48 KB
    if (!smem_set) {
        cudaFuncSetAttribute(harm_persist,
                             cudaFuncAttributeMaxDynamicSharedMemorySize,
                             smem_bytes);
        smem_set = 1;
    }

    xw_kernel<<<THARM, 256>>>(x, x2h);
    harm_persist<<<GRID_H, BLK_H, smem_bytes>>>(h2h, bias, gam, eps, hys, hzs);
    spike_kernel<<<128, 256>>>(us, spk, hys, hzs);
}